// round 12
// baseline (speedup 1.0000x reference)
#include <cuda_runtime.h>
#include <math.h>

#define N_PTS 16384            // 2*8192 points, both batches flattened
#define KNN 5
#define NC 32                  // cells per axis (3D)
#define NCELLS (NC * NC * NC)  // 32768
#define XMIN (-4.5f)
#define XMAXV (4.5f)
#define W (9.0f / NC)          // 0.28125
#define INV_W (NC / 9.0f)

#define MAIN_THREADS 64
#define MAIN_BLOCKS (N_PTS / MAIN_THREADS)   // 256, one source per THREAD

// ---- scratch (zero-initialized at module load; re-zeroed in-pipeline) ----
__device__ float4 g_tsort[N_PTS];   // (-2x,-2y,-2z,t^2) cell-ordered (linear z,y,x)
__device__ float4 g_ssort[N_PTS];   // (x,y,z, valid? s2 : -1) Morton-cell-ordered
__device__ int    g_thist[NCELLS];
__device__ int    g_shist[NCELLS];
__device__ int    g_tstart[NCELLS + 1];
__device__ int    g_tcur[NCELLS];
__device__ int    g_scur[NCELLS];
__device__ int    g_pubT[32], g_pubS[32];
__device__ int    g_flag[32];       // scan lookback flags (zeroed by finalize)
__device__ unsigned g_rowmask[NC];  // bit cy of word cz: target row (cz,cy) nonempty
__device__ float  g_bsum[MAIN_BLOCKS];
__device__ int    g_bcnt[MAIN_BLOCKS];

__device__ __forceinline__ int cell_coord(float v) {
    int c = (int)floorf((v - XMIN) * INV_W);
    return min(NC - 1, max(0, c));
}

__device__ __forceinline__ unsigned part1by2(unsigned v) {
    v &= 0x3FF;
    v = (v | (v << 16)) & 0x030000FF;
    v = (v | (v << 8))  & 0x0300F00F;
    v = (v | (v << 4))  & 0x030C30C3;
    v = (v | (v << 2))  & 0x09249249;
    return v;
}
__device__ __forceinline__ int morton3(int cx, int cy, int cz) {
    return (int)(part1by2(cx) | (part1by2(cy) << 1) | (part1by2(cz) << 2));
}

// ---------------------------------------------------------------------------
__global__ void hist_kernel(const float* __restrict__ src,
                            const float* __restrict__ tgt) {
    int gid = blockIdx.x * blockDim.x + threadIdx.x;   // 0..32767
    if (gid < N_PTS) {
        int cx = cell_coord(tgt[3 * gid]);
        int cy = cell_coord(tgt[3 * gid + 1]);
        int cz = cell_coord(tgt[3 * gid + 2]);
        atomicAdd(&g_thist[(cz * NC + cy) * NC + cx], 1);
    } else {
        int i = gid - N_PTS;
        int cx = cell_coord(src[3 * i]);
        int cy = cell_coord(src[3 * i + 1]);
        int cz = cell_coord(src[3 * i + 2]);
        atomicAdd(&g_shist[morton3(cx, cy, cz)], 1);
    }
}

// ---------------------------------------------------------------------------
// scan: ONE kernel, 32 co-resident blocks x 1024 threads, one cell/thread
// (coalesced). Block-local smem scan; cross-block offsets via publish +
// lookback spin. Emits tstart/tcur/scur + rowmask, re-zeroes histograms.
// ---------------------------------------------------------------------------
__global__ __launch_bounds__(1024) void scan_kernel() {
    __shared__ int pt[1024], ps[1024];
    __shared__ int vT[32], vS[32];
    __shared__ unsigned rowocc;
    const int tid = threadIdx.x, b = blockIdx.x;
    const int c = b * 1024 + tid;
    int tv = g_thist[c], sv = g_shist[c];
    if (tid == 0) rowocc = 0u;
    unsigned xbits = __ballot_sync(0xffffffffu, tv > 0);   // warp = one (z,y) row
    __syncthreads();
    if ((tid & 31) == 0 && xbits) atomicOr(&rowocc, 1u << (tid >> 5));
    pt[tid] = tv; ps[tid] = sv;
    __syncthreads();
    for (int off = 1; off < 1024; off <<= 1) {
        int ta = (tid >= off) ? pt[tid - off] : 0;
        int sa = (tid >= off) ? ps[tid - off] : 0;
        __syncthreads();
        pt[tid] += ta; ps[tid] += sa;
        __syncthreads();
    }
    if (tid == 1023) {
        g_pubT[b] = pt[1023];
        g_pubS[b] = ps[1023];
        __threadfence();
        *((volatile int*)&g_flag[b]) = 1;
        g_rowmask[b] = rowocc;          // block b == z-slab b
    }
    if (tid < 32) {
        int t = 0, s = 0;
        if (tid < b) {
            while (*((volatile int*)&g_flag[tid]) == 0) {}
            t = *((volatile int*)&g_pubT[tid]);
            s = *((volatile int*)&g_pubS[tid]);
        }
        vT[tid] = t; vS[tid] = s;
    }
    __syncthreads();
    int bofT = 0, bofS = 0;
    if (tid == 0) {
        for (int i = 0; i < 32; ++i) { bofT += vT[i]; bofS += vS[i]; }
        vT[0] = bofT; vS[0] = bofS;
    }
    __syncthreads();
    bofT = vT[0]; bofS = vS[0];
    int t = pt[tid] - tv + bofT;
    g_tstart[c] = t;  g_tcur[c] = t;
    g_scur[c] = ps[tid] - sv + bofS;
    g_thist[c] = 0;   g_shist[c] = 0;
    if (b == 31 && tid == 1023) g_tstart[NCELLS] = N_PTS;
}

// ---------------------------------------------------------------------------
__global__ void scatter_kernel(const float* __restrict__ src,
                               const float* __restrict__ tgt) {
    int gid = blockIdx.x * blockDim.x + threadIdx.x;
    if (gid < N_PTS) {
        float x = tgt[3 * gid], y = tgt[3 * gid + 1], z = tgt[3 * gid + 2];
        bool valid = (x != 0.0f) || (y != 0.0f) || (z != 0.0f);
        float t2 = fmaf(x, x, fmaf(y, y, z * z));
        float4 v;
        if (valid) { v.x = -2.0f * x; v.y = -2.0f * y; v.z = -2.0f * z; v.w = t2; }
        else       { v.x = 0.0f;      v.y = 0.0f;      v.z = 0.0f;      v.w = 1e30f; }
        int c = (cell_coord(z) * NC + cell_coord(y)) * NC + cell_coord(x);
        g_tsort[atomicAdd(&g_tcur[c], 1)] = v;
    } else {
        int i = gid - N_PTS;
        float x = src[3 * i], y = src[3 * i + 1], z = src[3 * i + 2];
        bool valid = (x != 0.0f) || (y != 0.0f) || (z != 0.0f);
        float s2 = fmaf(x, x, fmaf(y, y, z * z));
        float4 v; v.x = x; v.y = y; v.z = z; v.w = valid ? s2 : -1.0f;
        int c = morton3(cell_coord(x), cell_coord(y), cell_coord(z));
        g_ssort[atomicAdd(&g_scur[c], 1)] = v;
    }
}

// Branchless sorted insert, ascending m0..m4 (exact no-op when q >= m4).
__device__ __forceinline__ void insert5(float q, float& m0, float& m1,
                                        float& m2, float& m3, float& m4) {
    float t0 = fminf(m0, q);
    float t1 = fminf(m1, fmaxf(m0, q));
    float t2 = fminf(m2, fmaxf(m1, q));
    float t3 = fminf(m3, fmaxf(m2, q));
    float t4 = fminf(m4, fmaxf(m3, q));
    m0 = t0; m1 = t1; m2 = t2; m3 = t3; m4 = t4;
}

// ---------------------------------------------------------------------------
// Main: ONE SOURCE PER THREAD (Morton-consecutive lanes -> coherent work &
// shared L1 lines). Fully scalar per-lane traversal: seed = radius-1 cube
// (expand shells only if <5 candidates; rare), exact per-lane 5th -> tight
// r2, then sphere-minus-cube sweep with per-row exact r2 refresh.
// No warp merges, no ballots, no shared lists.
// ---------------------------------------------------------------------------
__global__ __launch_bounds__(MAIN_THREADS)
void knn_main() {
    __shared__ float red_s[MAIN_THREADS / 32];
    __shared__ int   red_c[MAIN_THREADS / 32];

    const int gid  = blockIdx.x * MAIN_THREADS + threadIdx.x;
    const int lane = threadIdx.x & 31;
    const int warp = threadIdx.x >> 5;

    float4 sv = g_ssort[gid];                    // coalesced
    const float sx = sv.x, sy = sv.y, sz = sv.z;
    const bool  valid = (sv.w >= 0.0f);
    const float s2 = fmaxf(sv.w, 0.0f);

    float m0 = 1e20f, m1 = 1e20f, m2 = 1e20f, m3 = 1e20f, m4 = 1e20f;

    if (valid) {
        const float px = fminf(fmaxf(sx, XMIN), XMAXV);
        const float py = fminf(fmaxf(sy, XMIN), XMAXV);
        const float pz = fminf(fmaxf(sz, XMIN), XMAXV);
        const int ccx = cell_coord(px);
        const int ccy = cell_coord(py);
        const int ccz = cell_coord(pz);

        int seen = 0;
        auto spanscan = [&](int cz, int cy, int cxl, int cxr) {
            int base = (cz * NC + cy) * NC;
            int st = g_tstart[base + cxl];
            int en = g_tstart[base + cxr + 1];
            seen += en - st;
            for (int i = st; i < en; ++i) {
                float4 v = g_tsort[i];
                float q = fmaf(sx, v.x, fmaf(sy, v.y, fmaf(sz, v.z, v.w)));
                insert5(q, m0, m1, m2, m3, m4);
            }
        };

        // ---- seed: radius-1 cube around home cell ----
        int rs = 1;
        {
            int zl = max(ccz - 1, 0), zh = min(ccz + 1, NC - 1);
            int yl = max(ccy - 1, 0), yh = min(ccy + 1, NC - 1);
            int xl = max(ccx - 1, 0), xh = min(ccx + 1, NC - 1);
            for (int cz = zl; cz <= zh; ++cz) {
                unsigned row = g_rowmask[cz];
                for (int cy = yl; cy <= yh; ++cy)
                    if ((row >> cy) & 1u) spanscan(cz, cy, xl, xh);
            }
        }
        // rare: expand shells until >=5 candidates
        while (seen < KNN && rs < NC) {
            ++rs;
            const int zA = ccz - rs, zB = ccz + rs;
            const int yA = ccy - rs, yB = ccy + rs;
            const int xA = ccx - rs, xB = ccx + rs;
            const int xl = max(xA, 0), xr = min(xB, NC - 1);
            for (int cz = max(zA, 0); cz <= min(zB, NC - 1); ++cz) {
                unsigned row = g_rowmask[cz];
                if (!row) continue;
                bool zface = (cz == zA) || (cz == zB);
                for (int cy = max(yA, 0); cy <= min(yB, NC - 1); ++cy) {
                    if (!((row >> cy) & 1u)) continue;
                    if (zface || cy == yA || cy == yB) {
                        spanscan(cz, cy, xl, xr);
                    } else {
                        if (xA >= 0)      spanscan(cz, cy, xA, xA);
                        if (xB <= NC - 1) spanscan(cz, cy, xB, xB);
                    }
                }
            }
        }

        // exact per-lane bound
        float r2 = m4 + s2;

        // ---- sphere pass minus the seed cube (radius rs) ----
        const int szA = ccz - rs, szB = ccz + rs;
        const int syA = ccy - rs, syB = ccy + rs;
        const int sxA = ccx - rs, sxB = ccx + rs;

        float rmax = sqrtf(r2);
        const int czmin = cell_coord(pz - rmax);
        const int czmax = cell_coord(pz + rmax);

        for (int cz = czmin; cz <= czmax; ++cz) {
            float zcmin = XMIN + cz * W;
            float dz = fmaxf(fmaxf(zcmin - pz, pz - (zcmin + W)), 0.0f);
            float dz2 = dz * dz;
            if (dz2 > r2) continue;
            unsigned row = g_rowmask[cz];
            if (!row) continue;
            float ry = sqrtf(r2 - dz2);
            const int cya = cell_coord(py - ry);
            const int cyb = cell_coord(py + ry);
            const bool zin = (cz >= szA) && (cz <= szB);
            for (int cy = cya; cy <= cyb; ++cy) {
                if (!((row >> cy) & 1u)) continue;
                float ycmin = XMIN + cy * W;
                float dy = fmaxf(fmaxf(ycmin - py, py - (ycmin + W)), 0.0f);
                float dd = fmaf(dy, dy, dz2);
                if (dd > r2) continue;
                float dxm = sqrtf(r2 - dd);
                int axl = cell_coord(px - dxm);
                int axr = cell_coord(px + dxm);
                if (zin && cy >= syA && cy <= syB) {
                    int r1 = min(axr, sxA - 1);
                    if (axl <= r1) spanscan(cz, cy, axl, r1);
                    int l2 = max(axl, sxB + 1);
                    if (l2 <= axr) spanscan(cz, cy, l2, axr);
                } else {
                    spanscan(cz, cy, axl, axr);
                }
                r2 = fminf(r2, m4 + s2);   // exact per-lane refresh (2 instr)
            }
        }
    }

    // epilogue: per-lane loss contribution, warp + block reduce
    float sum = 0.0f; int cnt = 0;
    if (valid) {
        sum = sqrtf(fmaxf(m0 + s2, 1e-12f))
            + sqrtf(fmaxf(m1 + s2, 1e-12f))
            + sqrtf(fmaxf(m2 + s2, 1e-12f))
            + sqrtf(fmaxf(m3 + s2, 1e-12f))
            + sqrtf(fmaxf(m4 + s2, 1e-12f));
        cnt = 1;
    }
#pragma unroll
    for (int off = 16; off > 0; off >>= 1) {
        sum += __shfl_xor_sync(0xffffffffu, sum, off);
        cnt += __shfl_xor_sync(0xffffffffu, cnt, off);
    }
    if (lane == 0) { red_s[warp] = sum; red_c[warp] = cnt; }
    __syncthreads();
    if (threadIdx.x == 0) {
        float bs = 0.0f; int bc = 0;
#pragma unroll
        for (int w = 0; w < MAIN_THREADS / 32; ++w) { bs += red_s[w]; bc += red_c[w]; }
        g_bsum[blockIdx.x] = bs;
        g_bcnt[blockIdx.x] = bc;
    }
}

// ---------------------------------------------------------------------------
__global__ __launch_bounds__(256) void finalize_kernel(float* __restrict__ out) {
    __shared__ double ds[256];
    __shared__ int    di[256];
    int tid = threadIdx.x;
    ds[tid] = (tid < MAIN_BLOCKS) ? (double)g_bsum[tid] : 0.0;
    di[tid] = (tid < MAIN_BLOCKS) ? g_bcnt[tid] : 0;
    __syncthreads();
#pragma unroll
    for (int off = 128; off > 0; off >>= 1) {
        if (tid < off) { ds[tid] += ds[tid + off]; di[tid] += di[tid + off]; }
        __syncthreads();
    }
    if (tid == 0) out[0] = (float)(ds[0] / ((double)di[0] * KNN));
    if (tid < 32) g_flag[tid] = 0;    // reset scan lookback flags for next call
}

// ---------------------------------------------------------------------------
extern "C" void kernel_launch(void* const* d_in, const int* in_sizes, int n_in,
                              void* d_out, int out_size) {
    const float* src = (const float*)d_in[0];  // source_pc (2,8192,3)
    const float* tgt = (const float*)d_in[1];  // target_pc (2,8192,3)
    float* out = (float*)d_out;

    hist_kernel<<<2 * N_PTS / 256, 256>>>(src, tgt);     // launch 0
    scan_kernel<<<32, 1024>>>();                         // launch 1
    scatter_kernel<<<2 * N_PTS / 256, 256>>>(src, tgt);  // launch 2
    knn_main<<<MAIN_BLOCKS, MAIN_THREADS>>>();           // launch 3 (profiled)
    finalize_kernel<<<1, 256>>>(out);                    // launch 4
}